// round 15
// baseline (speedup 1.0000x reference)
#include <cuda_runtime.h>
#include <stdint.h>
#include <math.h>

#define BB 32
#define TXX 384
#define TYY 1536
#define DIMK 256
#define NF 80
#define NEGF (-1000000000.0f)
#define CONSTF (-73.51508265637381f)   /* -0.5*log(2*pi)*80 */

#define ATTN_SZ ((size_t)BB * TXX * TYY)

// DP ring: 32 rows = 4 blocks of 8 rows (R8 single-warp design)
#define DSLOT 32
#define BLK_BYTES (8 * TXX * 4)   /* 12288 */
#define MBAR_OFF (DSLOT * TXX * 4)     /* 49152 */
#define DP_SMEM  (MBAR_OFF + 48)
#define CROSS_SMEM (2 * 80 * 128 * 4)  /* 81920 */
#define FUSED_SMEM CROSS_SMEM

#define DECROWS (TYY + 8)
#define DEC_BYTES (DECROWS * 32 * 2)   /* 98816 per batch */
#define BT_SMEM (DEC_BYTES + 16)

#define NYT 12                    /* y bands of 128 */
#define NCROSS (NYT * BB * 3)     /* 1152 cross tiles */

// ---------------- scratch (static device memory; no allocation) -------------
__device__ float g_xp[(size_t)BB * NF * TXX];          // [b][f][t]
__device__ float g_xsq[BB * TXX];
__device__ float g_ysq[BB * TYY];
__device__ float g_v[(size_t)BB * TYY * TXX];          // [b][y][t]
__device__ unsigned short g_dec[(size_t)BB * DECROWS * 32];  // decision bits
__device__ int   g_idx[BB * TYY];
__device__ float g_dur[BB * TXX];
__device__ int   g_cnt[BB * NYT];                      // cross progress counters

// ---------------------------------------------------------------------------
// y_square + zero progress counters (runs before fused kernel every call)
__global__ void ysq_kernel(const float* __restrict__ y) {
    int b = blockIdx.y;
    int s = blockIdx.x * 256 + threadIdx.x;
    if (blockIdx.x == 0 && blockIdx.y == 0) {
        for (int i = threadIdx.x; i < BB * NYT; i += 256) g_cnt[i] = 0;
    }
    if (s >= TYY) return;
    const float* yb = y + (size_t)b * NF * TYY + s;
    float sum = 0.f;
#pragma unroll
    for (int f = 0; f < NF; ++f) {
        float v = yb[(size_t)f * TYY];
        sum += v * v;
    }
    g_ysq[b * TYY + s] = -0.5f * sum;
}

// ---------------------------------------------------------------------------
// xp[b][f][t] = sum_d x[b][t][d] * W[f][d] + bias[f];  xsq[b][t] = -0.5*sum_f xp^2
__global__ __launch_bounds__(160) void xp_kernel(const float* __restrict__ x,
                                                 const float* __restrict__ W,
                                                 const float* __restrict__ bias) {
    __shared__ float xs[32][128];
    __shared__ float ws[32][80];
    __shared__ float part[10][128];

    int b  = blockIdx.y;
    int t0 = blockIdx.x * 128;
    int tid = threadIdx.x;
    int tx = tid & 15;
    int fg = tid >> 4;

    float acc[8][8];
#pragma unroll
    for (int i = 0; i < 8; ++i)
#pragma unroll
        for (int j = 0; j < 8; ++j) acc[i][j] = 0.f;

    const float* xb = x + ((size_t)b * TXX + t0) * DIMK;

    for (int k0 = 0; k0 < DIMK; k0 += 32) {
        for (int i = tid; i < 1024; i += 160) {
            int t = i >> 3, kq = i & 7;
            float4 v = *(const float4*)(xb + (size_t)t * DIMK + k0 + kq * 4);
            xs[kq * 4 + 0][t] = v.x; xs[kq * 4 + 1][t] = v.y;
            xs[kq * 4 + 2][t] = v.z; xs[kq * 4 + 3][t] = v.w;
        }
        for (int i = tid; i < 640; i += 160) {
            int f = i >> 3, kq = i & 7;
            float4 v = *(const float4*)(W + (size_t)f * DIMK + k0 + kq * 4);
            ws[kq * 4 + 0][f] = v.x; ws[kq * 4 + 1][f] = v.y;
            ws[kq * 4 + 2][f] = v.z; ws[kq * 4 + 3][f] = v.w;
        }
        __syncthreads();
#pragma unroll 8
        for (int kk = 0; kk < 32; ++kk) {
            float4 xa = *(const float4*)&xs[kk][tx * 8];
            float4 xb4 = *(const float4*)&xs[kk][tx * 8 + 4];
            float4 wa = *(const float4*)&ws[kk][fg * 8];
            float4 wb4 = *(const float4*)&ws[kk][fg * 8 + 4];
            float xv[8] = {xa.x, xa.y, xa.z, xa.w, xb4.x, xb4.y, xb4.z, xb4.w};
            float wv[8] = {wa.x, wa.y, wa.z, wa.w, wb4.x, wb4.y, wb4.z, wb4.w};
#pragma unroll
            for (int i = 0; i < 8; ++i)
#pragma unroll
                for (int j = 0; j < 8; ++j) acc[i][j] += xv[i] * wv[j];
        }
        __syncthreads();
    }

    float bv[8];
#pragma unroll
    for (int j = 0; j < 8; ++j) bv[j] = bias[fg * 8 + j];

    float ss[8];
#pragma unroll
    for (int i = 0; i < 8; ++i) ss[i] = 0.f;

#pragma unroll
    for (int i = 0; i < 8; ++i) {
        int t = t0 + tx * 8 + i;
#pragma unroll
        for (int j = 0; j < 8; ++j) {
            float v = acc[i][j] + bv[j];
            g_xp[((size_t)b * NF + fg * 8 + j) * TXX + t] = v;
            ss[i] += v * v;
        }
    }
#pragma unroll
    for (int i = 0; i < 8; ++i) part[fg][tx * 8 + i] = ss[i];
    __syncthreads();
    if (tid < 128) {
        float s = 0.f;
#pragma unroll
        for (int g = 0; g < 10; ++g) s += part[g][tid];
        g_xsq[b * TXX + t0 + tid] = -0.5f * s;
    }
}

// ---------------------------------------------------------------------------
__device__ __forceinline__ int mbar_try_wait(uint32_t mb, uint32_t par) {
    uint32_t done;
    asm volatile(
        "{\n\t.reg .pred p;\n\t"
        "mbarrier.try_wait.parity.acquire.cta.shared::cta.b64 p, [%1], %2, 0x989680;\n\t"
        "selp.b32 %0,1,0,p;\n\t}"
        : "=r"(done) : "r"(mb), "r"(par) : "memory");
    return (int)done;
}

// ---------------------------------------------------------------------------
// FUSED kernel: blocks [0,BB) = dp forward (1 warp, R8 ring, decisions ->
// global g_dec so dp smem is only 48KB and cross keeps 2 blocks/SM);
// blocks [BB,..) = cross tiles, band-major, bumping g_cnt when done.
__global__ __launch_bounds__(256) void fused_kernel(const float* __restrict__ y,
                                                    const int* __restrict__ xl,
                                                    const int* __restrict__ yl) {
    extern __shared__ float sm[];

    if (blockIdx.x >= BB) {
        // ================= cross tile =================
        int idx = blockIdx.x - BB;
        int yi  = idx / (BB * 3);
        int rem = idx - yi * (BB * 3);
        int b   = rem / 3;
        int t0  = (rem - b * 3) * 128;
        int y0  = yi * 128;
        int ylen = yl[b], xlen = xl[b];
        if (y0 >= ylen) return;
        if (t0 >= xlen) return;
        if (t0 > y0 + 128) return;

        float* Ys = sm;            // [80][128]
        float* Xs = sm + 80 * 128; // [80][128]
        int tid = threadIdx.x;

        const float* yb = y + (size_t)b * NF * TYY;
        for (int i = tid; i < 2560; i += 256) {
            int f = i >> 5, q = i & 31;
            *(float4*)&Ys[f * 128 + q * 4] =
                *(const float4*)(yb + (size_t)f * TYY + y0 + q * 4);
        }
        const float* xpb = g_xp + (size_t)b * NF * TXX;
        for (int i = tid; i < 2560; i += 256) {
            int f = i >> 5, q = i & 31;
            *(float4*)&Xs[f * 128 + q * 4] =
                *(const float4*)(xpb + (size_t)f * TXX + t0 + q * 4);
        }
        __syncthreads();

        int tx = tid & 15;
        int ty = tid >> 4;

        unsigned long long acc2[8][4];
#pragma unroll
        for (int i = 0; i < 8; ++i)
#pragma unroll
            for (int j = 0; j < 4; ++j) acc2[i][j] = 0ull;

#pragma unroll 4
        for (int f = 0; f < NF; ++f) {
            float4 ya = *(const float4*)&Ys[f * 128 + ty * 8];
            float4 yb4 = *(const float4*)&Ys[f * 128 + ty * 8 + 4];
            float4 xa = *(const float4*)&Xs[f * 128 + tx * 8];
            float4 xb4 = *(const float4*)&Xs[f * 128 + tx * 8 + 4];
            unsigned long long xp0, xp1, xp2, xp3;
            asm("mov.b64 %0,{%1,%2};" : "=l"(xp0) : "f"(xa.x),  "f"(xa.y));
            asm("mov.b64 %0,{%1,%2};" : "=l"(xp1) : "f"(xa.z),  "f"(xa.w));
            asm("mov.b64 %0,{%1,%2};" : "=l"(xp2) : "f"(xb4.x), "f"(xb4.y));
            asm("mov.b64 %0,{%1,%2};" : "=l"(xp3) : "f"(xb4.z), "f"(xb4.w));
            float yv[8] = {ya.x, ya.y, ya.z, ya.w, yb4.x, yb4.y, yb4.z, yb4.w};
#pragma unroll
            for (int i = 0; i < 8; ++i) {
                unsigned long long yd;
                asm("mov.b64 %0,{%1,%1};" : "=l"(yd) : "f"(yv[i]));
                asm("fma.rn.f32x2 %0,%1,%2,%0;" : "+l"(acc2[i][0]) : "l"(yd), "l"(xp0));
                asm("fma.rn.f32x2 %0,%1,%2,%0;" : "+l"(acc2[i][1]) : "l"(yd), "l"(xp1));
                asm("fma.rn.f32x2 %0,%1,%2,%0;" : "+l"(acc2[i][2]) : "l"(yd), "l"(xp2));
                asm("fma.rn.f32x2 %0,%1,%2,%0;" : "+l"(acc2[i][3]) : "l"(yd), "l"(xp3));
            }
        }

        int tbase = t0 + tx * 8;
        float xsqv[8];
#pragma unroll
        for (int j = 0; j < 8; ++j) xsqv[j] = g_xsq[b * TXX + tbase + j];

#pragma unroll
        for (int i = 0; i < 8; ++i) {
            int yg = y0 + ty * 8 + i;
            if (yg >= ylen) continue;
            float ysv = g_ysq[b * TYY + yg];
            float av[8];
#pragma unroll
            for (int j2 = 0; j2 < 4; ++j2) {
                float lo, hi;
                asm("mov.b64 {%0,%1}, %2;" : "=f"(lo), "=f"(hi) : "l"(acc2[i][j2]));
                av[j2 * 2] = lo; av[j2 * 2 + 1] = hi;
            }
            float ov[8];
#pragma unroll
            for (int j = 0; j < 8; ++j) {
                float val = ((ysv + av[j]) + xsqv[j]) + CONSTF;
                ov[j] = (tbase + j < xlen) ? val : NEGF;
            }
            float* vout = g_v + ((size_t)b * TYY + yg) * TXX + tbase;
            *(float4*)(vout + 0) = make_float4(ov[0], ov[1], ov[2], ov[3]);
            *(float4*)(vout + 4) = make_float4(ov[4], ov[5], ov[6], ov[7]);
        }
        __syncthreads();
        if (tid == 0) {
            __threadfence();
            atomicAdd(&g_cnt[b * NYT + yi], 1);
        }
        return;
    }

    // ================= dp forward (R8 single-warp + band gating) ==========
    if (threadIdx.x >= 32) return;
    float* ring = sm;                                        // [DSLOT][TXX]

    int b = blockIdx.x;
    int lane = threadIdx.x;
    int ylen = yl[b], xlen = xl[b];
    (void)xlen;

    const float* vb = g_v + (size_t)b * TYY * TXX;
    unsigned short* dec = g_dec + (size_t)b * DECROWS * 32;
    uint32_t ring_base = (uint32_t)__cvta_generic_to_shared(ring);
    uint32_t mbar_addr = ring_base + MBAR_OFF;

    if (lane == 0) {
#pragma unroll
        for (int m = 0; m < 4; ++m)
            asm volatile("mbarrier.init.shared.b64 [%0], 1;"
                         :: "r"(mbar_addr + m * 8) : "memory");
    }
    __syncwarp();
    asm volatile("fence.proxy.async.shared::cta;" ::: "memory");

    const volatile int* cp = (const volatile int*)&g_cnt[b * NYT];
    int gated = -1;

#define DP_GATE(bi_)                                                           \
    do {                                                                       \
        int row_ = (bi_) * 8;                                                  \
        if (row_ < ylen) {                                                     \
            int band_ = row_ >> 7;                                             \
            if (band_ > gated) {                                               \
                int exp_ = 2 + ((band_ >= 1 && xlen > 256) ? 1 : 0);           \
                while (cp[band_] < exp_) { }                                   \
                __threadfence();                                               \
                gated = band_;                                                 \
            }                                                                  \
        }                                                                      \
    } while (0)

#define DP_ISSUE(bi_)                                                          \
    do {                                                                       \
        if (lane == 0) {                                                       \
            int r0_ = (bi_) * 8;                                               \
            if (r0_ + 8 > TYY) r0_ = TYY - 8;                                  \
            uint32_t mb_ = mbar_addr + ((bi_) & 3) * 8;                        \
            uint32_t dst_ = ring_base + (uint32_t)(((bi_) & 3) * BLK_BYTES);   \
            const float* src_ = vb + (size_t)r0_ * TXX;                        \
            asm volatile("mbarrier.arrive.expect_tx.shared.b64 _, [%0], %1;"   \
                         :: "r"(mb_), "r"((uint32_t)BLK_BYTES) : "memory");    \
            asm volatile(                                                      \
                "cp.async.bulk.shared::cta.global.mbarrier::complete_tx::bytes"\
                " [%0], [%1], %2, [%3];"                                       \
                :: "r"(dst_), "l"(src_), "r"((uint32_t)BLK_BYTES), "r"(mb_)    \
                : "memory");                                                   \
        }                                                                      \
    } while (0)

#define DP_WAIT(bi_)                                                           \
    do {                                                                       \
        uint32_t mb_ = mbar_addr + ((bi_) & 3) * 8;                            \
        uint32_t par_ = (uint32_t)(((bi_) >> 2) & 1);                          \
        while (!mbar_try_wait(mb_, par_)) { }                                  \
    } while (0)

    DP_GATE(0); DP_ISSUE(0);
    DP_GATE(1); DP_ISSUE(1);

    float q[12];
#pragma unroll
    for (int j = 0; j < 12; ++j) q[j] = NEGF;
    if (lane == 0) q[0] = 0.0f;

    for (int yb2 = 0; yb2 < ylen; yb2 += 8) {
        int bi = yb2 >> 3;
        DP_GATE(bi + 2);
        DP_ISSUE(bi + 2);
        DP_WAIT(bi);

#pragma unroll
        for (int h = 0; h < 2; ++h) {
            float4 r0[4], r1[4], r2[4];
#pragma unroll
            for (int k = 0; k < 4; ++k) {
                const float4* rp = (const float4*)(ring +
                    ((yb2 + h * 4 + k) & (DSLOT - 1)) * TXX + lane * 12);
                r0[k] = rp[0]; r1[k] = rp[1]; r2[k] = rp[2];
            }
#pragma unroll
            for (int k = 0; k < 4; ++k) {
                int yy = yb2 + h * 4 + k;
                float carry = __shfl_up_sync(0xffffffffu, q[11], 1);
                if (lane == 0) carry = NEGF;
                float vv[12] = {r0[k].x, r0[k].y, r0[k].z, r0[k].w,
                                r1[k].x, r1[k].y, r1[k].z, r1[k].w,
                                r2[k].x, r2[k].y, r2[k].z, r2[k].w};
                unsigned bits = 0u;
#pragma unroll
                for (int j = 11; j >= 1; --j)
                    bits |= ((q[j] < q[j - 1]) ? 1u : 0u) << j;
                bits |= (q[0] < carry) ? 1u : 0u;
#pragma unroll
                for (int j = 11; j >= 1; --j)
                    q[j] = vv[j] + fmaxf(q[j], q[j - 1]);
                q[0] = vv[0] + fmaxf(q[0], carry);
                dec[(size_t)yy * 32 + lane] = (unsigned short)bits;
            }
        }
    }
    {
        int bl = (ylen - 1) >> 3;
        DP_WAIT(bl + 1);
        DP_WAIT(bl + 2);
    }
}

// ---------------------------------------------------------------------------
// Backtrack kernel: one warp per batch; bulk-copy this batch's decision
// region (98816B) into smem, then R8 scalar backtrack.
__global__ __launch_bounds__(32) void bt_kernel(const int* __restrict__ xl,
                                                const int* __restrict__ yl) {
    extern __shared__ unsigned short sdec[];    // [DECROWS][32]
    int b = blockIdx.x;
    int lane = threadIdx.x;
    int ylen = yl[b], xlen = xl[b];

    uint32_t smem_base = (uint32_t)__cvta_generic_to_shared(sdec);
    uint32_t mbar_addr = smem_base + DEC_BYTES;

    if (lane == 0) {
        asm volatile("mbarrier.init.shared.b64 [%0], 1;" :: "r"(mbar_addr) : "memory");
    }
    __syncwarp();
    asm volatile("fence.proxy.async.shared::cta;" ::: "memory");
    if (lane == 0) {
        const unsigned short* src = g_dec + (size_t)b * DECROWS * 32;
        asm volatile("mbarrier.arrive.expect_tx.shared.b64 _, [%0], %1;"
                     :: "r"(mbar_addr), "r"((uint32_t)DEC_BYTES) : "memory");
        asm volatile(
            "cp.async.bulk.shared::cta.global.mbarrier::complete_tx::bytes"
            " [%0], [%1], %2, [%3];"
            :: "r"(smem_base), "l"(src), "r"((uint32_t)DEC_BYTES), "r"(mbar_addr)
            : "memory");
    }
    while (!mbar_try_wait(mbar_addr, 0)) { }

#pragma unroll
    for (int j = 0; j < 12; ++j) g_dur[b * TXX + lane * 12 + j] = 0.0f;
    __syncwarp();

    if (lane == 0) {
        int idx = xlen - 1;
        int w = idx / 12, r = idx - w * 12;
        int cnt = 0;
        int* gi = g_idx + b * TYY;
        int yy = ylen - 1;
        while (yy >= 0) {
            int w0 = w;
            unsigned wa[8], wb2[8];
            if (yy >= 7) {
#pragma unroll
                for (int k = 0; k < 8; ++k)
                    wa[k] = (unsigned)sdec[(yy - k) * 32 + w0];
                if (w0 > 0) {
#pragma unroll
                    for (int k = 0; k < 8; ++k)
                        wb2[k] = (unsigned)sdec[(yy - k) * 32 + (w0 - 1)];
                } else {
#pragma unroll
                    for (int k = 0; k < 8; ++k) wb2[k] = 0u;
                }
#pragma unroll
                for (int k = 0; k < 8; ++k) {
                    int row = yy - k;
                    unsigned use = (w == w0) ? wa[k] : wb2[k];
                    gi[row] = idx;
                    cnt++;
                    bool move = (idx != 0) && (row > 0) &&
                                ((idx == row) || (((use >> r) & 1u) != 0u));
                    if (move) {
                        g_dur[b * TXX + idx] = (float)cnt;
                        cnt = 0; idx--;
                        if (--r < 0) { r = 11; w--; }
                    }
                }
                yy -= 8;
            } else {
                int row = yy;
                unsigned use = (unsigned)sdec[row * 32 + w];
                gi[row] = idx;
                cnt++;
                bool move = (idx != 0) && (row > 0) &&
                            ((idx == row) || (((use >> r) & 1u) != 0u));
                if (move) {
                    g_dur[b * TXX + idx] = (float)cnt;
                    cnt = 0; idx--;
                    if (--r < 0) { r = 11; w--; }
                }
                yy -= 1;
            }
        }
        g_dur[b * TXX + idx] = (float)cnt;
    }
}

// ---------------------------------------------------------------------------
// attn[b][t][s] = (s < ylen && g_idx[b][s] == t) ? 1 : 0
__global__ __launch_bounds__(128) void attn_kernel(const int* __restrict__ yl,
                                                   float* __restrict__ out) {
    int b = blockIdx.y;
    int t = blockIdx.x;
    int tid = threadIdx.x;
    int ylen = yl[b];
    const int* gi = g_idx + b * TYY;
    float* o = out + ((size_t)b * TXX + t) * TYY;
#pragma unroll
    for (int it = 0; it < 3; ++it) {
        int s4 = tid + it * 128;
        int s = s4 * 4;
        int4 iv = *(const int4*)(gi + s);
        float4 ov;
        ov.x = (s + 0 < ylen && iv.x == t) ? 1.f : 0.f;
        ov.y = (s + 1 < ylen && iv.y == t) ? 1.f : 0.f;
        ov.z = (s + 2 < ylen && iv.z == t) ? 1.f : 0.f;
        ov.w = (s + 3 < ylen && iv.w == t) ? 1.f : 0.f;
        *(float4*)(o + s) = ov;
    }
}

// ---------------------------------------------------------------------------
// loss + durations tail
__global__ __launch_bounds__(256) void loss_kernel(const float* __restrict__ pred,
                                                   const int* __restrict__ xl,
                                                   float* __restrict__ out,
                                                   int write_tail) {
    __shared__ float red[256];
    int tid = threadIdx.x;
    float s = 0.f;
    for (int i = tid; i < BB * TXX; i += 256) {
        int b = i / TXX, t = i - b * TXX;
        float dur = g_dur[i];
        float tl = (t < xl[b]) ? logf(dur + 1e-8f) : 0.0f;
        float d = pred[i] - tl;
        s += d * d;
        if (write_tail) out[ATTN_SZ + 1 + i] = dur;
    }
    red[tid] = s;
    __syncthreads();
    for (int off = 128; off > 0; off >>= 1) {
        if (tid < off) red[tid] += red[tid + off];
        __syncthreads();
    }
    if (tid == 0 && write_tail) {
        int sx = 0;
        for (int bb2 = 0; bb2 < BB; ++bb2) sx += xl[bb2];
        out[ATTN_SZ] = red[0] / (float)sx;
    }
}

// ---------------------------------------------------------------------------
extern "C" void kernel_launch(void* const* d_in, const int* in_sizes, int n_in,
                              void* d_out, int out_size) {
    const float* x    = (const float*)d_in[0];
    const float* y    = (const float*)d_in[1];
    const int*   xlen = (const int*)d_in[4];
    const int*   ylen = (const int*)d_in[5];
    const float* pred = (const float*)d_in[6];
    const float* W    = (const float*)d_in[7];
    const float* bias = (const float*)d_in[8];
    float* out = (float*)d_out;

    cudaFuncSetAttribute(fused_kernel, cudaFuncAttributeMaxDynamicSharedMemorySize,
                         FUSED_SMEM);
    cudaFuncSetAttribute(bt_kernel, cudaFuncAttributeMaxDynamicSharedMemorySize,
                         BT_SMEM);

    ysq_kernel<<<dim3(TYY / 256, BB), 256>>>(y);
    xp_kernel<<<dim3(TXX / 128, BB), 160>>>(x, W, bias);
    fused_kernel<<<BB + NCROSS, 256, FUSED_SMEM>>>(y, xlen, ylen);
    bt_kernel<<<BB, 32, BT_SMEM>>>(xlen, ylen);
    attn_kernel<<<dim3(TXX, BB), 128>>>(ylen, out);

    int write_tail = ((size_t)out_size >= ATTN_SZ + 1 + BB * TXX) ? 1 : 0;
    loss_kernel<<<1, 256>>>(pred, xlen, out, write_tail);
}